// round 5
// baseline (speedup 1.0000x reference)
#include <cuda_runtime.h>
#include <cuda_bf16.h>
#include <cstdint>

// ---------------------------------------------------------------------------
// Problem constants
// ---------------------------------------------------------------------------
static constexpr int E_  = 8;
static constexpr int H_  = 1024;
static constexpr int FF_ = 4096;
static constexpr int T_  = 32768;
static constexpr int G_  = T_ / E_;     // 4096 tokens per expert

// GEMM tiling: CTA 128x256, 8 warps (2 M x 4 N), warp tile 64x64
static constexpr int BM = 128;
static constexpr int BN = 256;
static constexpr int BK = 32;           // bf16 elems per K-stage
static constexpr int PITCH = 80;        // SMEM row pitch bytes (64B data + 16B pad)
static constexpr int OFF_AL = BM * PITCH;                 // 10240
static constexpr int OFF_BH = 2 * BM * PITCH;             // 20480
static constexpr int OFF_BL = OFF_BH + BN * PITCH;        // 40960
static constexpr int STAGE_BYTES = OFF_BL + BN * PITCH;   // 61440
static constexpr int NSTAGE = 3;
static constexpr int SMEM_TOTAL = NSTAGE * STAGE_BYTES;   // 184320

// ---------------------------------------------------------------------------
// Device scratch (static globals: the sanctioned no-alloc scratch mechanism)
// ---------------------------------------------------------------------------
__device__ __nv_bfloat16 g_XH[(size_t)T_ * H_];
__device__ __nv_bfloat16 g_XL[(size_t)T_ * H_];
__device__ __nv_bfloat16 g_W1H[(size_t)E_ * FF_ * H_];
__device__ __nv_bfloat16 g_W1L[(size_t)E_ * FF_ * H_];
__device__ __nv_bfloat16 g_W2TH[(size_t)E_ * H_ * FF_];
__device__ __nv_bfloat16 g_W2TL[(size_t)E_ * H_ * FF_];
__device__ __nv_bfloat16 g_HH[(size_t)T_ * FF_];
__device__ __nv_bfloat16 g_HL[(size_t)T_ * FF_];

// ---------------------------------------------------------------------------
// PTX helpers (family-safe: sm_80-era instructions only)
// ---------------------------------------------------------------------------
__device__ __forceinline__ uint32_t smem_u32(const void* p) {
    uint32_t a;
    asm("{ .reg .u64 t; cvta.to.shared.u64 t, %1; cvt.u32.u64 %0, t; }" : "=r"(a) : "l"(p));
    return a;
}

__device__ __forceinline__ void cp16(uint32_t dst, const void* src) {
    asm volatile("cp.async.cg.shared.global [%0], [%1], 16;" :: "r"(dst), "l"(src) : "memory");
}
#define CP_COMMIT() asm volatile("cp.async.commit_group;" ::: "memory")
#define CP_WAIT2()  asm volatile("cp.async.wait_group 2;" ::: "memory")

__device__ __forceinline__ void ldsm4(uint32_t& r0, uint32_t& r1, uint32_t& r2, uint32_t& r3,
                                      uint32_t addr) {
    asm volatile("ldmatrix.sync.aligned.m8n8.x4.shared.b16 {%0,%1,%2,%3}, [%4];"
                 : "=r"(r0), "=r"(r1), "=r"(r2), "=r"(r3) : "r"(addr));
}

__device__ __forceinline__ void mma16816(float* d, const uint32_t* a, const uint32_t* b) {
    asm volatile(
        "mma.sync.aligned.m16n8k16.row.col.f32.bf16.bf16.f32 "
        "{%0,%1,%2,%3}, {%4,%5,%6,%7}, {%8,%9}, {%0,%1,%2,%3};"
        : "+f"(d[0]), "+f"(d[1]), "+f"(d[2]), "+f"(d[3])
        : "r"(a[0]), "r"(a[1]), "r"(a[2]), "r"(a[3]), "r"(b[0]), "r"(b[1]));
}

// ---------------------------------------------------------------------------
// fp32 -> bf16 hi/lo split helpers + kernels
// ---------------------------------------------------------------------------
__device__ __forceinline__ uint32_t pack2(__nv_bfloat16 a, __nv_bfloat16 b) {
    return (uint32_t)__bfloat16_as_ushort(a) | ((uint32_t)__bfloat16_as_ushort(b) << 16);
}
__device__ __forceinline__ void split1(float v, __nv_bfloat16& h, __nv_bfloat16& l) {
    h = __float2bfloat16(v);
    l = __float2bfloat16(v - __bfloat162float(h));
}

__global__ void split_kernel(const float* __restrict__ in,
                             __nv_bfloat16* __restrict__ hi,
                             __nv_bfloat16* __restrict__ lo, int n4) {
    for (int i = blockIdx.x * blockDim.x + threadIdx.x; i < n4; i += gridDim.x * blockDim.x) {
        float4 v = reinterpret_cast<const float4*>(in)[i];
        __nv_bfloat16 h0, h1, h2, h3, l0, l1, l2, l3;
        split1(v.x, h0, l0); split1(v.y, h1, l1);
        split1(v.z, h2, l2); split1(v.w, h3, l3);
        uint2 hp, lp;
        hp.x = pack2(h0, h1); hp.y = pack2(h2, h3);
        lp.x = pack2(l0, l1); lp.y = pack2(l2, l3);
        reinterpret_cast<uint2*>(hi)[i] = hp;
        reinterpret_cast<uint2*>(lo)[i] = lp;
    }
}

// w2 [E, FF, H] -> w2t [E, H, FF] (bf16 hi/lo), 32x32 SMEM tile transpose
__global__ void transpose_split(const float* __restrict__ in,
                                __nv_bfloat16* __restrict__ oh,
                                __nv_bfloat16* __restrict__ ol) {
    __shared__ float t[32][33];
    const int e  = blockIdx.z;
    const int h0 = blockIdx.x * 32;
    const int f0 = blockIdx.y * 32;
    const float* src = in + (size_t)e * FF_ * H_;
#pragma unroll
    for (int j = 0; j < 4; j++)
        t[threadIdx.y + j * 8][threadIdx.x] =
            src[(size_t)(f0 + threadIdx.y + j * 8) * H_ + h0 + threadIdx.x];
    __syncthreads();
    __nv_bfloat16* dh = oh + (size_t)e * H_ * FF_;
    __nv_bfloat16* dl = ol + (size_t)e * H_ * FF_;
#pragma unroll
    for (int j = 0; j < 4; j++) {
        float v = t[threadIdx.x][threadIdx.y + j * 8];
        __nv_bfloat16 h, l;
        split1(v, h, l);
        size_t o = (size_t)(h0 + threadIdx.y + j * 8) * FF_ + f0 + threadIdx.x;
        dh[o] = h; dl[o] = l;
    }
}

// ---------------------------------------------------------------------------
// TN grouped GEMM: C[M,N] = A[M,K] @ B[N,K]^T  (bf16 hi/lo 3-term, fp32 accum)
// CTA tile 128x256; 8 warps as 2(M) x 4(N); warp tile 64x64; mma m16n8k16.
// Fragment schedule keeps <=164 live regs: ah+bh resident, al transient,
// bl reuses bh registers.
// MODE 0: epilogue = relu + bf16 hi/lo split into Ch/Cl (pitch FF_)
// MODE 1: epilogue = fp32 store into Cf (pitch H_)
// ---------------------------------------------------------------------------
template <int KDIM, int MODE>
__global__ void __launch_bounds__(256, 1)
gemm_bf16x3(const __nv_bfloat16* __restrict__ Ah, const __nv_bfloat16* __restrict__ Al, int lda,
            const __nv_bfloat16* __restrict__ Bh, const __nv_bfloat16* __restrict__ Bl, int ldb,
            int bExpStride,
            __nv_bfloat16* __restrict__ Ch, __nv_bfloat16* __restrict__ Cl,
            float* __restrict__ Cf) {
    extern __shared__ char smem[];
    const uint32_t sbase = smem_u32(smem);
    const int tid  = threadIdx.x;
    const int lane = tid & 31;
    const int warp = tid >> 5;
    const int wm = warp & 1;           // 0..1 (M)
    const int wn = warp >> 1;          // 0..3 (N)
    const int aRow0 = blockIdx.z * G_ + blockIdx.y * BM;
    const int bRow0 = blockIdx.z * bExpStride + blockIdx.x * BN;
    const int col0  = blockIdx.x * BN;
    constexpr int S = KDIM / BK;

    float acc[4][8][4];
#pragma unroll
    for (int i = 0; i < 4; i++)
#pragma unroll
        for (int j = 0; j < 8; j++)
#pragma unroll
            for (int q = 0; q < 4; q++) acc[i][j][q] = 0.f;

    // stage loader: A 512 chunks(16B) x2(hi/lo), B 1024 x2 -> 12 cp16/thread
    auto load_stage = [&](int s, int buf) {
        const uint32_t st = sbase + buf * STAGE_BYTES;
        const int k0 = s * BK;
#pragma unroll
        for (int i = 0; i < 2; i++) {
            int c = tid + i * 256;
            int r = c >> 2, q = c & 3;
            uint32_t so = (uint32_t)(r * PITCH + q * 16);
            size_t ga = (size_t)(aRow0 + r) * lda + k0 + q * 8;
            cp16(st + so,          Ah + ga);
            cp16(st + OFF_AL + so, Al + ga);
        }
#pragma unroll
        for (int i = 0; i < 4; i++) {
            int c = tid + i * 256;
            int r = c >> 2, q = c & 3;
            uint32_t so = (uint32_t)(r * PITCH + q * 16);
            size_t gb = (size_t)(bRow0 + r) * ldb + k0 + q * 8;
            cp16(st + OFF_BH + so, Bh + gb);
            cp16(st + OFF_BL + so, Bl + gb);
        }
    };

    // lane-fixed parts of ldmatrix addresses
    const uint32_t aLane = (uint32_t)((wm * 64 + (lane & 15)) * PITCH + (lane >> 4) * 16);
    const uint32_t bLane = (uint32_t)((wn * 64 + (lane & 15)) * PITCH + (lane >> 4) * 16);

    load_stage(0, 0); CP_COMMIT();
    load_stage(1, 1); CP_COMMIT();

    for (int s = 0; s < S; s++) {
        if (s + 2 < S) load_stage(s + 2, (s + 2) % NSTAGE);
        CP_COMMIT();
        CP_WAIT2();
        __syncthreads();

        const uint32_t st = sbase + (s % NSTAGE) * STAGE_BYTES;
#pragma unroll
        for (int ks = 0; ks < 2; ks++) {               // two k16 steps per stage
            const uint32_t kOff = (uint32_t)(ks * 32); // 16 elems * 2B
            uint32_t ah[4][4], bx[8][2];
            // resident A-hi fragments
#pragma unroll
            for (int i = 0; i < 4; i++) {
                uint32_t ad = st + aLane + kOff + (uint32_t)(i * 16 * PITCH);
                ldsm4(ah[i][0], ah[i][1], ah[i][2], ah[i][3], ad);
            }
            // bx <- B hi
#pragma unroll
            for (int jj = 0; jj < 4; jj++) {
                uint32_t bd = st + OFF_BH + bLane + kOff + (uint32_t)(jj * 16 * PITCH);
                uint32_t r0, r1, r2, r3;
                ldsm4(r0, r1, r2, r3, bd);
                bx[jj * 2 + 0][0] = r0; bx[jj * 2 + 1][0] = r1;
                bx[jj * 2 + 0][1] = r2; bx[jj * 2 + 1][1] = r3;
            }
            // hi*hi
#pragma unroll
            for (int i = 0; i < 4; i++)
#pragma unroll
                for (int j = 0; j < 8; j++) mma16816(acc[i][j], ah[i], bx[j]);
            // lo*hi : A-lo fragments transient (4 regs at a time)
#pragma unroll
            for (int i = 0; i < 4; i++) {
                uint32_t al4[4];
                uint32_t ad = st + OFF_AL + aLane + kOff + (uint32_t)(i * 16 * PITCH);
                ldsm4(al4[0], al4[1], al4[2], al4[3], ad);
#pragma unroll
                for (int j = 0; j < 8; j++) mma16816(acc[i][j], al4, bx[j]);
            }
            // bx <- B lo (reuse registers)
#pragma unroll
            for (int jj = 0; jj < 4; jj++) {
                uint32_t bd = st + OFF_BL + bLane + kOff + (uint32_t)(jj * 16 * PITCH);
                uint32_t r0, r1, r2, r3;
                ldsm4(r0, r1, r2, r3, bd);
                bx[jj * 2 + 0][0] = r0; bx[jj * 2 + 1][0] = r1;
                bx[jj * 2 + 0][1] = r2; bx[jj * 2 + 1][1] = r3;
            }
            // hi*lo
#pragma unroll
            for (int i = 0; i < 4; i++)
#pragma unroll
                for (int j = 0; j < 8; j++) mma16816(acc[i][j], ah[i], bx[j]);
        }
        __syncthreads();
    }

    // ---- epilogue (register -> global) ------------------------------------
    const int rBase = aRow0 + wm * 64 + (lane >> 2);
    const int cBase = col0 + wn * 64 + 2 * (lane & 3);
    if (MODE == 0) {
        uint32_t* gH = reinterpret_cast<uint32_t*>(Ch);
        uint32_t* gL = reinterpret_cast<uint32_t*>(Cl);
#pragma unroll
        for (int i = 0; i < 4; i++)
#pragma unroll
            for (int j = 0; j < 8; j++) {
                int r0 = rBase + i * 16;
                int c  = cBase + j * 8;
                float v0 = fmaxf(acc[i][j][0], 0.f), v1 = fmaxf(acc[i][j][1], 0.f);
                float v2 = fmaxf(acc[i][j][2], 0.f), v3 = fmaxf(acc[i][j][3], 0.f);
                __nv_bfloat16 h0, l0, h1, l1, h2, l2, h3, l3;
                split1(v0, h0, l0); split1(v1, h1, l1);
                split1(v2, h2, l2); split1(v3, h3, l3);
                size_t w0 = ((size_t)r0 * FF_ + c) >> 1;
                size_t w1 = ((size_t)(r0 + 8) * FF_ + c) >> 1;
                gH[w0] = pack2(h0, h1); gL[w0] = pack2(l0, l1);
                gH[w1] = pack2(h2, h3); gL[w1] = pack2(l2, l3);
            }
    } else {
#pragma unroll
        for (int i = 0; i < 4; i++)
#pragma unroll
            for (int j = 0; j < 8; j++) {
                int r0 = rBase + i * 16;
                int c  = cBase + j * 8;
                float2 p0 = make_float2(acc[i][j][0], acc[i][j][1]);
                float2 p1 = make_float2(acc[i][j][2], acc[i][j][3]);
                *reinterpret_cast<float2*>(&Cf[(size_t)r0 * H_ + c])       = p0;
                *reinterpret_cast<float2*>(&Cf[(size_t)(r0 + 8) * H_ + c]) = p1;
            }
    }
}

// ---------------------------------------------------------------------------
// Host launcher
// ---------------------------------------------------------------------------
extern "C" void kernel_launch(void* const* d_in, const int* in_sizes, int n_in,
                              void* d_out, int out_size) {
    (void)in_sizes; (void)n_in; (void)out_size;
    const float* x  = (const float*)d_in[0];
    const float* w1 = (const float*)d_in[1];
    const float* w2 = (const float*)d_in[2];
    float* out = (float*)d_out;

    void *xh, *xl, *w1h, *w1l, *w2th, *w2tl, *hh, *hl;
    cudaGetSymbolAddress(&xh,  g_XH);    cudaGetSymbolAddress(&xl,  g_XL);
    cudaGetSymbolAddress(&w1h, g_W1H);   cudaGetSymbolAddress(&w1l, g_W1L);
    cudaGetSymbolAddress(&w2th, g_W2TH); cudaGetSymbolAddress(&w2tl, g_W2TL);
    cudaGetSymbolAddress(&hh,  g_HH);    cudaGetSymbolAddress(&hl,  g_HL);

    cudaFuncSetAttribute(gemm_bf16x3<1024, 0>,
                         cudaFuncAttributeMaxDynamicSharedMemorySize, SMEM_TOTAL);
    cudaFuncSetAttribute(gemm_bf16x3<4096, 1>,
                         cudaFuncAttributeMaxDynamicSharedMemorySize, SMEM_TOTAL);

    // 1) fp32 -> bf16 hi/lo conversions
    split_kernel<<<2048, 256>>>(x, (__nv_bfloat16*)xh, (__nv_bfloat16*)xl, T_ * H_ / 4);
    split_kernel<<<2048, 256>>>(w1, (__nv_bfloat16*)w1h, (__nv_bfloat16*)w1l, E_ * FF_ * H_ / 4);
    transpose_split<<<dim3(H_ / 32, FF_ / 32, E_), dim3(32, 8)>>>(
        w2, (__nv_bfloat16*)w2th, (__nv_bfloat16*)w2tl);

    // 2) GEMM1: h = relu(x @ w1^T); A ld=H_, B ld=H_, B expert stride=FF_
    gemm_bf16x3<1024, 0><<<dim3(FF_ / BN, G_ / BM, E_), 256, SMEM_TOTAL>>>(
        (const __nv_bfloat16*)xh, (const __nv_bfloat16*)xl, H_,
        (const __nv_bfloat16*)w1h, (const __nv_bfloat16*)w1l, H_, FF_,
        (__nv_bfloat16*)hh, (__nv_bfloat16*)hl, nullptr);

    // 3) GEMM2: out = h @ w2 (w2 pre-transposed -> TN); B expert stride=H_
    gemm_bf16x3<4096, 1><<<dim3(H_ / BN, G_ / BM, E_), 256, SMEM_TOTAL>>>(
        (const __nv_bfloat16*)hh, (const __nv_bfloat16*)hl, FF_,
        (const __nv_bfloat16*)w2th, (const __nv_bfloat16*)w2tl, FF_, H_,
        nullptr, nullptr, out);
}

// round 6
// speedup vs baseline: 1.0002x; 1.0002x over previous
#include <cuda_runtime.h>
#include <cuda_bf16.h>
#include <cstdint>

// ---------------------------------------------------------------------------
// Problem constants
// ---------------------------------------------------------------------------
static constexpr int E_  = 8;
static constexpr int H_  = 1024;
static constexpr int FF_ = 4096;
static constexpr int T_  = 32768;
static constexpr int G_  = T_ / E_;     // 4096 tokens per expert

// GEMM tiling: CTA 128x256, 8 warps (2 M x 4 N), warp tile 64x64
static constexpr int BM = 128;
static constexpr int BN = 256;
static constexpr int BK = 32;           // bf16 elems per K-stage
static constexpr int PITCH = 80;        // SMEM row pitch bytes (64B data + 16B pad)
static constexpr int OFF_AL = BM * PITCH;                 // 10240
static constexpr int OFF_BH = 2 * BM * PITCH;             // 20480
static constexpr int OFF_BL = OFF_BH + BN * PITCH;        // 40960
static constexpr int STAGE_BYTES = OFF_BL + BN * PITCH;   // 61440
static constexpr int NSTAGE = 3;
static constexpr int SMEM_TOTAL = NSTAGE * STAGE_BYTES;   // 184320

// ---------------------------------------------------------------------------
// Device scratch (static globals: the sanctioned no-alloc scratch mechanism)
// ---------------------------------------------------------------------------
__device__ __nv_bfloat16 g_XH[(size_t)T_ * H_];
__device__ __nv_bfloat16 g_XL[(size_t)T_ * H_];
__device__ __nv_bfloat16 g_W1H[(size_t)E_ * FF_ * H_];
__device__ __nv_bfloat16 g_W1L[(size_t)E_ * FF_ * H_];
__device__ __nv_bfloat16 g_W2TH[(size_t)E_ * H_ * FF_];
__device__ __nv_bfloat16 g_W2TL[(size_t)E_ * H_ * FF_];
__device__ __nv_bfloat16 g_HH[(size_t)T_ * FF_];
__device__ __nv_bfloat16 g_HL[(size_t)T_ * FF_];

// ---------------------------------------------------------------------------
// PTX helpers (family-safe: sm_80-era instructions only)
// ---------------------------------------------------------------------------
__device__ __forceinline__ uint32_t smem_u32(const void* p) {
    uint32_t a;
    asm("{ .reg .u64 t; cvta.to.shared.u64 t, %1; cvt.u32.u64 %0, t; }" : "=r"(a) : "l"(p));
    return a;
}

__device__ __forceinline__ void cp16(uint32_t dst, const void* src) {
    asm volatile("cp.async.cg.shared.global [%0], [%1], 16;" :: "r"(dst), "l"(src) : "memory");
}
#define CP_COMMIT() asm volatile("cp.async.commit_group;" ::: "memory")
#define CP_WAIT2()  asm volatile("cp.async.wait_group 2;" ::: "memory")

__device__ __forceinline__ void ldsm4(uint32_t& r0, uint32_t& r1, uint32_t& r2, uint32_t& r3,
                                      uint32_t addr) {
    asm volatile("ldmatrix.sync.aligned.m8n8.x4.shared.b16 {%0,%1,%2,%3}, [%4];"
                 : "=r"(r0), "=r"(r1), "=r"(r2), "=r"(r3) : "r"(addr));
}

__device__ __forceinline__ void mma16816(float* d, const uint32_t* a, const uint32_t* b) {
    asm volatile(
        "mma.sync.aligned.m16n8k16.row.col.f32.bf16.bf16.f32 "
        "{%0,%1,%2,%3}, {%4,%5,%6,%7}, {%8,%9}, {%0,%1,%2,%3};"
        : "+f"(d[0]), "+f"(d[1]), "+f"(d[2]), "+f"(d[3])
        : "r"(a[0]), "r"(a[1]), "r"(a[2]), "r"(a[3]), "r"(b[0]), "r"(b[1]));
}

// ---------------------------------------------------------------------------
// fp32 -> bf16 hi/lo split helpers + kernels
// ---------------------------------------------------------------------------
__device__ __forceinline__ uint32_t pack2(__nv_bfloat16 a, __nv_bfloat16 b) {
    return (uint32_t)__bfloat16_as_ushort(a) | ((uint32_t)__bfloat16_as_ushort(b) << 16);
}
__device__ __forceinline__ void split1(float v, __nv_bfloat16& h, __nv_bfloat16& l) {
    h = __float2bfloat16(v);
    l = __float2bfloat16(v - __bfloat162float(h));
}

__global__ void split_kernel(const float* __restrict__ in,
                             __nv_bfloat16* __restrict__ hi,
                             __nv_bfloat16* __restrict__ lo, int n4) {
    for (int i = blockIdx.x * blockDim.x + threadIdx.x; i < n4; i += gridDim.x * blockDim.x) {
        float4 v = reinterpret_cast<const float4*>(in)[i];
        __nv_bfloat16 h0, h1, h2, h3, l0, l1, l2, l3;
        split1(v.x, h0, l0); split1(v.y, h1, l1);
        split1(v.z, h2, l2); split1(v.w, h3, l3);
        uint2 hp, lp;
        hp.x = pack2(h0, h1); hp.y = pack2(h2, h3);
        lp.x = pack2(l0, l1); lp.y = pack2(l2, l3);
        reinterpret_cast<uint2*>(hi)[i] = hp;
        reinterpret_cast<uint2*>(lo)[i] = lp;
    }
}

// w2 [E, FF, H] -> w2t [E, H, FF] (bf16 hi/lo), 32x32 SMEM tile transpose
__global__ void transpose_split(const float* __restrict__ in,
                                __nv_bfloat16* __restrict__ oh,
                                __nv_bfloat16* __restrict__ ol) {
    __shared__ float t[32][33];
    const int e  = blockIdx.z;
    const int h0 = blockIdx.x * 32;
    const int f0 = blockIdx.y * 32;
    const float* src = in + (size_t)e * FF_ * H_;
#pragma unroll
    for (int j = 0; j < 4; j++)
        t[threadIdx.y + j * 8][threadIdx.x] =
            src[(size_t)(f0 + threadIdx.y + j * 8) * H_ + h0 + threadIdx.x];
    __syncthreads();
    __nv_bfloat16* dh = oh + (size_t)e * H_ * FF_;
    __nv_bfloat16* dl = ol + (size_t)e * H_ * FF_;
#pragma unroll
    for (int j = 0; j < 4; j++) {
        float v = t[threadIdx.x][threadIdx.y + j * 8];
        __nv_bfloat16 h, l;
        split1(v, h, l);
        size_t o = (size_t)(h0 + threadIdx.y + j * 8) * FF_ + f0 + threadIdx.x;
        dh[o] = h; dl[o] = l;
    }
}

// ---------------------------------------------------------------------------
// TN grouped GEMM: C[M,N] = A[M,K] @ B[N,K]^T  (bf16 hi/lo 3-term, fp32 accum)
// CTA tile 128x256; 8 warps as 2(M) x 4(N); warp tile 64x64; mma m16n8k16.
// 6-phase software pipeline per stage: every ldmatrix batch is issued just
// before an independent 32-MMA batch (distinct register buffers -> no WAR
// serialization), so LDSM latency/crossbar time hides under tensor issue.
// MODE 0: epilogue = relu + bf16 hi/lo split into Ch/Cl (pitch FF_)
// MODE 1: epilogue = fp32 store into Cf (pitch H_)
// ---------------------------------------------------------------------------
template <int KDIM, int MODE>
__global__ void __launch_bounds__(256, 1)
gemm_bf16x3(const __nv_bfloat16* __restrict__ Ah, const __nv_bfloat16* __restrict__ Al, int lda,
            const __nv_bfloat16* __restrict__ Bh, const __nv_bfloat16* __restrict__ Bl, int ldb,
            int bExpStride,
            __nv_bfloat16* __restrict__ Ch, __nv_bfloat16* __restrict__ Cl,
            float* __restrict__ Cf) {
    extern __shared__ char smem[];
    const uint32_t sbase = smem_u32(smem);
    const int tid  = threadIdx.x;
    const int lane = tid & 31;
    const int warp = tid >> 5;
    const int wm = warp & 1;           // 0..1 (M)
    const int wn = warp >> 1;          // 0..3 (N)
    const int aRow0 = blockIdx.z * G_ + blockIdx.y * BM;
    const int bRow0 = blockIdx.z * bExpStride + blockIdx.x * BN;
    const int col0  = blockIdx.x * BN;
    constexpr int S = KDIM / BK;

    float acc[4][8][4];
#pragma unroll
    for (int i = 0; i < 4; i++)
#pragma unroll
        for (int j = 0; j < 8; j++)
#pragma unroll
            for (int q = 0; q < 4; q++) acc[i][j][q] = 0.f;

    // stage loader: A 512 chunks(16B) x2(hi/lo), B 1024 x2 -> 12 cp16/thread
    auto load_stage = [&](int s, int buf) {
        const uint32_t st = sbase + buf * STAGE_BYTES;
        const int k0 = s * BK;
#pragma unroll
        for (int i = 0; i < 2; i++) {
            int c = tid + i * 256;
            int r = c >> 2, q = c & 3;
            uint32_t so = (uint32_t)(r * PITCH + q * 16);
            size_t ga = (size_t)(aRow0 + r) * lda + k0 + q * 8;
            cp16(st + so,          Ah + ga);
            cp16(st + OFF_AL + so, Al + ga);
        }
#pragma unroll
        for (int i = 0; i < 4; i++) {
            int c = tid + i * 256;
            int r = c >> 2, q = c & 3;
            uint32_t so = (uint32_t)(r * PITCH + q * 16);
            size_t gb = (size_t)(bRow0 + r) * ldb + k0 + q * 8;
            cp16(st + OFF_BH + so, Bh + gb);
            cp16(st + OFF_BL + so, Bl + gb);
        }
    };

    // lane-fixed parts of ldmatrix addresses
    const uint32_t aLane = (uint32_t)((wm * 64 + (lane & 15)) * PITCH + (lane >> 4) * 16);
    const uint32_t bLane = (uint32_t)((wn * 64 + (lane & 15)) * PITCH + (lane >> 4) * 16);

    // fragment buffers
    uint32_t ah[2][4][4];   // A-hi, double-buffered across k16 steps
    uint32_t bh[8][2];      // B-hi (single: reloaded only when dead)
    uint32_t al[4][4];      // A-lo
    uint32_t bl[8][2];      // B-lo

    auto ldA = [&](uint32_t base, uint32_t kOff, uint32_t (*dst)[4]) {
#pragma unroll
        for (int i = 0; i < 4; i++) {
            uint32_t ad = base + aLane + kOff + (uint32_t)(i * 16 * PITCH);
            ldsm4(dst[i][0], dst[i][1], dst[i][2], dst[i][3], ad);
        }
    };
    auto ldB = [&](uint32_t base, uint32_t kOff, uint32_t (*dst)[2]) {
#pragma unroll
        for (int jj = 0; jj < 4; jj++) {
            uint32_t bd = base + bLane + kOff + (uint32_t)(jj * 16 * PITCH);
            uint32_t r0, r1, r2, r3;
            ldsm4(r0, r1, r2, r3, bd);
            dst[jj * 2 + 0][0] = r0; dst[jj * 2 + 1][0] = r1;
            dst[jj * 2 + 0][1] = r2; dst[jj * 2 + 1][1] = r3;
        }
    };
    auto mmaBatch = [&](uint32_t (*a)[4], uint32_t (*b)[2]) {
#pragma unroll
        for (int i = 0; i < 4; i++)
#pragma unroll
            for (int j = 0; j < 8; j++) mma16816(acc[i][j], a[i], b[j]);
    };

    load_stage(0, 0); CP_COMMIT();
    load_stage(1, 1); CP_COMMIT();

    for (int s = 0; s < S; s++) {
        if (s + 2 < S) load_stage(s + 2, (s + 2) % NSTAGE);
        CP_COMMIT();
        CP_WAIT2();
        __syncthreads();

        const uint32_t st = sbase + (s % NSTAGE) * STAGE_BYTES;
        // stage-start: fragments for k16 step 0
        ldA(st, 0, ah[0]);
        ldB(st + OFF_BH, 0, bh);
        // P0: prefetch A-lo(k0), compute hi*hi(k0)
        ldA(st + OFF_AL, 0, al);
        mmaBatch(ah[0], bh);
        // P1: prefetch B-lo(k0), compute lo*hi(k0)
        ldB(st + OFF_BL, 0, bl);
        mmaBatch(al, bh);
        // P2: prefetch A-hi(k1)+B-hi(k1), compute hi*lo(k0)
        ldA(st, 32, ah[1]);
        ldB(st + OFF_BH, 32, bh);      // WAR vs P1 issue only
        mmaBatch(ah[0], bl);
        // P3: prefetch A-lo(k1), compute hi*hi(k1)
        ldA(st + OFF_AL, 32, al);
        mmaBatch(ah[1], bh);
        // P4: prefetch B-lo(k1), compute lo*hi(k1)
        ldB(st + OFF_BL, 32, bl);
        mmaBatch(al, bh);
        // P5: compute hi*lo(k1)
        mmaBatch(ah[1], bl);

        __syncthreads();
    }

    // ---- epilogue (register -> global) ------------------------------------
    const int rBase = aRow0 + wm * 64 + (lane >> 2);
    const int cBase = col0 + wn * 64 + 2 * (lane & 3);
    if (MODE == 0) {
        uint32_t* gH = reinterpret_cast<uint32_t*>(Ch);
        uint32_t* gL = reinterpret_cast<uint32_t*>(Cl);
#pragma unroll
        for (int i = 0; i < 4; i++)
#pragma unroll
            for (int j = 0; j < 8; j++) {
                int r0 = rBase + i * 16;
                int c  = cBase + j * 8;
                float v0 = fmaxf(acc[i][j][0], 0.f), v1 = fmaxf(acc[i][j][1], 0.f);
                float v2 = fmaxf(acc[i][j][2], 0.f), v3 = fmaxf(acc[i][j][3], 0.f);
                __nv_bfloat16 h0, l0, h1, l1, h2, l2, h3, l3;
                split1(v0, h0, l0); split1(v1, h1, l1);
                split1(v2, h2, l2); split1(v3, h3, l3);
                size_t w0 = ((size_t)r0 * FF_ + c) >> 1;
                size_t w1 = ((size_t)(r0 + 8) * FF_ + c) >> 1;
                gH[w0] = pack2(h0, h1); gL[w0] = pack2(l0, l1);
                gH[w1] = pack2(h2, h3); gL[w1] = pack2(l2, l3);
            }
    } else {
#pragma unroll
        for (int i = 0; i < 4; i++)
#pragma unroll
            for (int j = 0; j < 8; j++) {
                int r0 = rBase + i * 16;
                int c  = cBase + j * 8;
                float2 p0 = make_float2(acc[i][j][0], acc[i][j][1]);
                float2 p1 = make_float2(acc[i][j][2], acc[i][j][3]);
                *reinterpret_cast<float2*>(&Cf[(size_t)r0 * H_ + c])       = p0;
                *reinterpret_cast<float2*>(&Cf[(size_t)(r0 + 8) * H_ + c]) = p1;
            }
    }
}

// ---------------------------------------------------------------------------
// Host launcher
// ---------------------------------------------------------------------------
extern "C" void kernel_launch(void* const* d_in, const int* in_sizes, int n_in,
                              void* d_out, int out_size) {
    (void)in_sizes; (void)n_in; (void)out_size;
    const float* x  = (const float*)d_in[0];
    const float* w1 = (const float*)d_in[1];
    const float* w2 = (const float*)d_in[2];
    float* out = (float*)d_out;

    void *xh, *xl, *w1h, *w1l, *w2th, *w2tl, *hh, *hl;
    cudaGetSymbolAddress(&xh,  g_XH);    cudaGetSymbolAddress(&xl,  g_XL);
    cudaGetSymbolAddress(&w1h, g_W1H);   cudaGetSymbolAddress(&w1l, g_W1L);
    cudaGetSymbolAddress(&w2th, g_W2TH); cudaGetSymbolAddress(&w2tl, g_W2TL);
    cudaGetSymbolAddress(&hh,  g_HH);    cudaGetSymbolAddress(&hl,  g_HL);

    cudaFuncSetAttribute(gemm_bf16x3<1024, 0>,
                         cudaFuncAttributeMaxDynamicSharedMemorySize, SMEM_TOTAL);
    cudaFuncSetAttribute(gemm_bf16x3<4096, 1>,
                         cudaFuncAttributeMaxDynamicSharedMemorySize, SMEM_TOTAL);

    // 1) fp32 -> bf16 hi/lo conversions
    split_kernel<<<2048, 256>>>(x, (__nv_bfloat16*)xh, (__nv_bfloat16*)xl, T_ * H_ / 4);
    split_kernel<<<2048, 256>>>(w1, (__nv_bfloat16*)w1h, (__nv_bfloat16*)w1l, E_ * FF_ * H_ / 4);
    transpose_split<<<dim3(H_ / 32, FF_ / 32, E_), dim3(32, 8)>>>(
        w2, (__nv_bfloat16*)w2th, (__nv_bfloat16*)w2tl);

    // 2) GEMM1: h = relu(x @ w1^T); A ld=H_, B ld=H_, B expert stride=FF_
    gemm_bf16x3<1024, 0><<<dim3(FF_ / BN, G_ / BM, E_), 256, SMEM_TOTAL>>>(
        (const __nv_bfloat16*)xh, (const __nv_bfloat16*)xl, H_,
        (const __nv_bfloat16*)w1h, (const __nv_bfloat16*)w1l, H_, FF_,
        (__nv_bfloat16*)hh, (__nv_bfloat16*)hl, nullptr);

    // 3) GEMM2: out = h @ w2 (w2 pre-transposed -> TN); B expert stride=H_
    gemm_bf16x3<4096, 1><<<dim3(H_ / BN, G_ / BM, E_), 256, SMEM_TOTAL>>>(
        (const __nv_bfloat16*)hh, (const __nv_bfloat16*)hl, FF_,
        (const __nv_bfloat16*)w2th, (const __nv_bfloat16*)w2tl, FF_, H_,
        nullptr, nullptr, out);
}

// round 7
// speedup vs baseline: 1.0012x; 1.0011x over previous
#include <cuda_runtime.h>
#include <cuda_bf16.h>
#include <cstdint>

// ---------------------------------------------------------------------------
// Problem constants
// ---------------------------------------------------------------------------
static constexpr int E_  = 8;
static constexpr int H_  = 1024;
static constexpr int FF_ = 4096;
static constexpr int T_  = 32768;
static constexpr int G_  = T_ / E_;     // 4096 tokens per expert

// GEMM tiling: CTA 128x256, 16 warps (4 M x 4 N), warp tile 32x64
static constexpr int BM = 128;
static constexpr int BN = 256;
static constexpr int BK = 32;           // bf16 elems per K-stage
static constexpr int PITCH = 80;        // SMEM row pitch bytes (64B data + 16B pad)
static constexpr int OFF_AL = BM * PITCH;                 // 10240
static constexpr int OFF_BH = 2 * BM * PITCH;             // 20480
static constexpr int OFF_BL = OFF_BH + BN * PITCH;        // 40960
static constexpr int STAGE_BYTES = OFF_BL + BN * PITCH;   // 61440
static constexpr int NSTAGE = 3;
static constexpr int SMEM_TOTAL = NSTAGE * STAGE_BYTES;   // 184320
static constexpr int NTHREADS = 512;

// ---------------------------------------------------------------------------
// Device scratch (static globals: the sanctioned no-alloc scratch mechanism)
// ---------------------------------------------------------------------------
__device__ __nv_bfloat16 g_XH[(size_t)T_ * H_];
__device__ __nv_bfloat16 g_XL[(size_t)T_ * H_];
__device__ __nv_bfloat16 g_W1H[(size_t)E_ * FF_ * H_];
__device__ __nv_bfloat16 g_W1L[(size_t)E_ * FF_ * H_];
__device__ __nv_bfloat16 g_W2TH[(size_t)E_ * H_ * FF_];
__device__ __nv_bfloat16 g_W2TL[(size_t)E_ * H_ * FF_];
__device__ __nv_bfloat16 g_HH[(size_t)T_ * FF_];
__device__ __nv_bfloat16 g_HL[(size_t)T_ * FF_];

// ---------------------------------------------------------------------------
// PTX helpers (family-safe: sm_80-era instructions only)
// ---------------------------------------------------------------------------
__device__ __forceinline__ uint32_t smem_u32(const void* p) {
    uint32_t a;
    asm("{ .reg .u64 t; cvta.to.shared.u64 t, %1; cvt.u32.u64 %0, t; }" : "=r"(a) : "l"(p));
    return a;
}

__device__ __forceinline__ void cp16(uint32_t dst, const void* src) {
    asm volatile("cp.async.cg.shared.global [%0], [%1], 16;" :: "r"(dst), "l"(src) : "memory");
}
#define CP_COMMIT() asm volatile("cp.async.commit_group;" ::: "memory")
#define CP_WAIT2()  asm volatile("cp.async.wait_group 2;" ::: "memory")

__device__ __forceinline__ void ldsm4(uint32_t& r0, uint32_t& r1, uint32_t& r2, uint32_t& r3,
                                      uint32_t addr) {
    asm volatile("ldmatrix.sync.aligned.m8n8.x4.shared.b16 {%0,%1,%2,%3}, [%4];"
                 : "=r"(r0), "=r"(r1), "=r"(r2), "=r"(r3) : "r"(addr));
}

__device__ __forceinline__ void mma16816(float* d, const uint32_t* a, const uint32_t* b) {
    asm volatile(
        "mma.sync.aligned.m16n8k16.row.col.f32.bf16.bf16.f32 "
        "{%0,%1,%2,%3}, {%4,%5,%6,%7}, {%8,%9}, {%0,%1,%2,%3};"
        : "+f"(d[0]), "+f"(d[1]), "+f"(d[2]), "+f"(d[3])
        : "r"(a[0]), "r"(a[1]), "r"(a[2]), "r"(a[3]), "r"(b[0]), "r"(b[1]));
}

// ---------------------------------------------------------------------------
// fp32 -> bf16 hi/lo split helpers + kernels
// ---------------------------------------------------------------------------
__device__ __forceinline__ uint32_t pack2(__nv_bfloat16 a, __nv_bfloat16 b) {
    return (uint32_t)__bfloat16_as_ushort(a) | ((uint32_t)__bfloat16_as_ushort(b) << 16);
}
__device__ __forceinline__ void split1(float v, __nv_bfloat16& h, __nv_bfloat16& l) {
    h = __float2bfloat16(v);
    l = __float2bfloat16(v - __bfloat162float(h));
}

__global__ void split_kernel(const float* __restrict__ in,
                             __nv_bfloat16* __restrict__ hi,
                             __nv_bfloat16* __restrict__ lo, int n4) {
    for (int i = blockIdx.x * blockDim.x + threadIdx.x; i < n4; i += gridDim.x * blockDim.x) {
        float4 v = reinterpret_cast<const float4*>(in)[i];
        __nv_bfloat16 h0, h1, h2, h3, l0, l1, l2, l3;
        split1(v.x, h0, l0); split1(v.y, h1, l1);
        split1(v.z, h2, l2); split1(v.w, h3, l3);
        uint2 hp, lp;
        hp.x = pack2(h0, h1); hp.y = pack2(h2, h3);
        lp.x = pack2(l0, l1); lp.y = pack2(l2, l3);
        reinterpret_cast<uint2*>(hi)[i] = hp;
        reinterpret_cast<uint2*>(lo)[i] = lp;
    }
}

// w2 [E, FF, H] -> w2t [E, H, FF] (bf16 hi/lo), 32x32 SMEM tile transpose
__global__ void transpose_split(const float* __restrict__ in,
                                __nv_bfloat16* __restrict__ oh,
                                __nv_bfloat16* __restrict__ ol) {
    __shared__ float t[32][33];
    const int e  = blockIdx.z;
    const int h0 = blockIdx.x * 32;
    const int f0 = blockIdx.y * 32;
    const float* src = in + (size_t)e * FF_ * H_;
#pragma unroll
    for (int j = 0; j < 4; j++)
        t[threadIdx.y + j * 8][threadIdx.x] =
            src[(size_t)(f0 + threadIdx.y + j * 8) * H_ + h0 + threadIdx.x];
    __syncthreads();
    __nv_bfloat16* dh = oh + (size_t)e * H_ * FF_;
    __nv_bfloat16* dl = ol + (size_t)e * H_ * FF_;
#pragma unroll
    for (int j = 0; j < 4; j++) {
        float v = t[threadIdx.x][threadIdx.y + j * 8];
        __nv_bfloat16 h, l;
        split1(v, h, l);
        size_t o = (size_t)(h0 + threadIdx.y + j * 8) * FF_ + f0 + threadIdx.x;
        dh[o] = h; dl[o] = l;
    }
}

// ---------------------------------------------------------------------------
// TN grouped GEMM: C[M,N] = A[M,K] @ B[N,K]^T  (bf16 hi/lo 3-term, fp32 accum)
// CTA tile 128x256; 16 warps as 4(M) x 4(N); warp tile 32x64; mma m16n8k16.
// 4 warps per SMSP (occ 25%) hide ldsm/barrier latency; ~150 live regs,
// no spills.
// MODE 0: epilogue = relu + bf16 hi/lo split into Ch/Cl (pitch FF_)
// MODE 1: epilogue = fp32 store into Cf (pitch H_)
// ---------------------------------------------------------------------------
template <int KDIM, int MODE>
__global__ void __launch_bounds__(NTHREADS, 1)
gemm_bf16x3(const __nv_bfloat16* __restrict__ Ah, const __nv_bfloat16* __restrict__ Al, int lda,
            const __nv_bfloat16* __restrict__ Bh, const __nv_bfloat16* __restrict__ Bl, int ldb,
            int bExpStride,
            __nv_bfloat16* __restrict__ Ch, __nv_bfloat16* __restrict__ Cl,
            float* __restrict__ Cf) {
    extern __shared__ char smem[];
    const uint32_t sbase = smem_u32(smem);
    const int tid  = threadIdx.x;
    const int lane = tid & 31;
    const int warp = tid >> 5;
    const int wm = warp & 3;           // 0..3 (M, 32 rows each)
    const int wn = warp >> 2;          // 0..3 (N, 64 cols each)
    const int aRow0 = blockIdx.z * G_ + blockIdx.y * BM;
    const int bRow0 = blockIdx.z * bExpStride + blockIdx.x * BN;
    const int col0  = blockIdx.x * BN;
    constexpr int S = KDIM / BK;

    float acc[2][8][4];
#pragma unroll
    for (int i = 0; i < 2; i++)
#pragma unroll
        for (int j = 0; j < 8; j++)
#pragma unroll
            for (int q = 0; q < 4; q++) acc[i][j][q] = 0.f;

    // stage loader: 3072 16B chunks total -> 6 cp16 per thread
    auto load_stage = [&](int s, int buf) {
        const uint32_t st = sbase + buf * STAGE_BYTES;
        const int k0 = s * BK;
        {
            int r = tid >> 2, q = tid & 3;              // A: 512 chunks per matrix
            uint32_t so = (uint32_t)(r * PITCH + q * 16);
            size_t ga = (size_t)(aRow0 + r) * lda + k0 + q * 8;
            cp16(st + so,          Ah + ga);
            cp16(st + OFF_AL + so, Al + ga);
        }
#pragma unroll
        for (int i = 0; i < 2; i++) {                   // B: 1024 chunks per matrix
            int c = tid + i * NTHREADS;
            int r = c >> 2, q = c & 3;
            uint32_t so = (uint32_t)(r * PITCH + q * 16);
            size_t gb = (size_t)(bRow0 + r) * ldb + k0 + q * 8;
            cp16(st + OFF_BH + so, Bh + gb);
            cp16(st + OFF_BL + so, Bl + gb);
        }
    };

    // lane-fixed parts of ldmatrix addresses
    const uint32_t aLane = (uint32_t)((wm * 32 + (lane & 15)) * PITCH + (lane >> 4) * 16);
    const uint32_t bLane = (uint32_t)((wn * 64 + (lane & 15)) * PITCH + (lane >> 4) * 16);

    load_stage(0, 0); CP_COMMIT();
    load_stage(1, 1); CP_COMMIT();

    for (int s = 0; s < S; s++) {
        if (s + 2 < S) load_stage(s + 2, (s + 2) % NSTAGE);
        CP_COMMIT();
        CP_WAIT2();
        __syncthreads();

        const uint32_t st = sbase + (s % NSTAGE) * STAGE_BYTES;
#pragma unroll
        for (int ks = 0; ks < 2; ks++) {               // two k16 steps per stage
            const uint32_t kOff = (uint32_t)(ks * 32); // 16 elems * 2B
            uint32_t ah[2][4], al[2][4], bh[8][2], bl[8][2];
#pragma unroll
            for (int i = 0; i < 2; i++) {
                uint32_t ad = st + aLane + kOff + (uint32_t)(i * 16 * PITCH);
                ldsm4(ah[i][0], ah[i][1], ah[i][2], ah[i][3], ad);
                ldsm4(al[i][0], al[i][1], al[i][2], al[i][3], ad + OFF_AL);
            }
#pragma unroll
            for (int jj = 0; jj < 4; jj++) {
                uint32_t bd = st + OFF_BH + bLane + kOff + (uint32_t)(jj * 16 * PITCH);
                uint32_t r0, r1, r2, r3;
                ldsm4(r0, r1, r2, r3, bd);
                bh[jj * 2 + 0][0] = r0; bh[jj * 2 + 1][0] = r1;
                bh[jj * 2 + 0][1] = r2; bh[jj * 2 + 1][1] = r3;
                ldsm4(r0, r1, r2, r3, bd + (OFF_BL - OFF_BH));
                bl[jj * 2 + 0][0] = r0; bl[jj * 2 + 1][0] = r1;
                bl[jj * 2 + 0][1] = r2; bl[jj * 2 + 1][1] = r3;
            }
#pragma unroll
            for (int i = 0; i < 2; i++)
#pragma unroll
                for (int j = 0; j < 8; j++) mma16816(acc[i][j], ah[i], bh[j]); // hi*hi
#pragma unroll
            for (int i = 0; i < 2; i++)
#pragma unroll
                for (int j = 0; j < 8; j++) mma16816(acc[i][j], al[i], bh[j]); // lo*hi
#pragma unroll
            for (int i = 0; i < 2; i++)
#pragma unroll
                for (int j = 0; j < 8; j++) mma16816(acc[i][j], ah[i], bl[j]); // hi*lo
        }
        __syncthreads();
    }

    // ---- epilogue (register -> global) ------------------------------------
    const int rBase = aRow0 + wm * 32 + (lane >> 2);
    const int cBase = col0 + wn * 64 + 2 * (lane & 3);
    if (MODE == 0) {
        uint32_t* gH = reinterpret_cast<uint32_t*>(Ch);
        uint32_t* gL = reinterpret_cast<uint32_t*>(Cl);
#pragma unroll
        for (int i = 0; i < 2; i++)
#pragma unroll
            for (int j = 0; j < 8; j++) {
                int r0 = rBase + i * 16;
                int c  = cBase + j * 8;
                float v0 = fmaxf(acc[i][j][0], 0.f), v1 = fmaxf(acc[i][j][1], 0.f);
                float v2 = fmaxf(acc[i][j][2], 0.f), v3 = fmaxf(acc[i][j][3], 0.f);
                __nv_bfloat16 h0, l0, h1, l1, h2, l2, h3, l3;
                split1(v0, h0, l0); split1(v1, h1, l1);
                split1(v2, h2, l2); split1(v3, h3, l3);
                size_t w0 = ((size_t)r0 * FF_ + c) >> 1;
                size_t w1 = ((size_t)(r0 + 8) * FF_ + c) >> 1;
                gH[w0] = pack2(h0, h1); gL[w0] = pack2(l0, l1);
                gH[w1] = pack2(h2, h3); gL[w1] = pack2(l2, l3);
            }
    } else {
#pragma unroll
        for (int i = 0; i < 2; i++)
#pragma unroll
            for (int j = 0; j < 8; j++) {
                int r0 = rBase + i * 16;
                int c  = cBase + j * 8;
                float2 p0 = make_float2(acc[i][j][0], acc[i][j][1]);
                float2 p1 = make_float2(acc[i][j][2], acc[i][j][3]);
                *reinterpret_cast<float2*>(&Cf[(size_t)r0 * H_ + c])       = p0;
                *reinterpret_cast<float2*>(&Cf[(size_t)(r0 + 8) * H_ + c]) = p1;
            }
    }
}

// ---------------------------------------------------------------------------
// Host launcher
// ---------------------------------------------------------------------------
extern "C" void kernel_launch(void* const* d_in, const int* in_sizes, int n_in,
                              void* d_out, int out_size) {
    (void)in_sizes; (void)n_in; (void)out_size;
    const float* x  = (const float*)d_in[0];
    const float* w1 = (const float*)d_in[1];
    const float* w2 = (const float*)d_in[2];
    float* out = (float*)d_out;

    void *xh, *xl, *w1h, *w1l, *w2th, *w2tl, *hh, *hl;
    cudaGetSymbolAddress(&xh,  g_XH);    cudaGetSymbolAddress(&xl,  g_XL);
    cudaGetSymbolAddress(&w1h, g_W1H);   cudaGetSymbolAddress(&w1l, g_W1L);
    cudaGetSymbolAddress(&w2th, g_W2TH); cudaGetSymbolAddress(&w2tl, g_W2TL);
    cudaGetSymbolAddress(&hh,  g_HH);    cudaGetSymbolAddress(&hl,  g_HL);

    cudaFuncSetAttribute(gemm_bf16x3<1024, 0>,
                         cudaFuncAttributeMaxDynamicSharedMemorySize, SMEM_TOTAL);
    cudaFuncSetAttribute(gemm_bf16x3<4096, 1>,
                         cudaFuncAttributeMaxDynamicSharedMemorySize, SMEM_TOTAL);

    // 1) fp32 -> bf16 hi/lo conversions
    split_kernel<<<2048, 256>>>(x, (__nv_bfloat16*)xh, (__nv_bfloat16*)xl, T_ * H_ / 4);
    split_kernel<<<2048, 256>>>(w1, (__nv_bfloat16*)w1h, (__nv_bfloat16*)w1l, E_ * FF_ * H_ / 4);
    transpose_split<<<dim3(H_ / 32, FF_ / 32, E_), dim3(32, 8)>>>(
        w2, (__nv_bfloat16*)w2th, (__nv_bfloat16*)w2tl);

    // 2) GEMM1: h = relu(x @ w1^T); A ld=H_, B ld=H_, B expert stride=FF_
    gemm_bf16x3<1024, 0><<<dim3(FF_ / BN, G_ / BM, E_), NTHREADS, SMEM_TOTAL>>>(
        (const __nv_bfloat16*)xh, (const __nv_bfloat16*)xl, H_,
        (const __nv_bfloat16*)w1h, (const __nv_bfloat16*)w1l, H_, FF_,
        (__nv_bfloat16*)hh, (__nv_bfloat16*)hl, nullptr);

    // 3) GEMM2: out = h @ w2 (w2 pre-transposed -> TN); B expert stride=H_
    gemm_bf16x3<4096, 1><<<dim3(H_ / BN, G_ / BM, E_), NTHREADS, SMEM_TOTAL>>>(
        (const __nv_bfloat16*)hh, (const __nv_bfloat16*)hl, FF_,
        (const __nv_bfloat16*)w2th, (const __nv_bfloat16*)w2tl, FF_, H_,
        nullptr, nullptr, out);
}